// round 1
// baseline (speedup 1.0000x reference)
#include <cuda_runtime.h>

// Problem constants (fixed by the dataset: B=4, S=2048, D=1024, H=16)
#define B_  4
#define S_  2048
#define D_  1024
#define H_  16
#define DK_ 64
#define M_  (B_ * S_)   // 8192 rows for the projection GEMMs

// ---------------------------------------------------------------------------
// Scratch (device globals; no allocation allowed in kernel_launch)
// ---------------------------------------------------------------------------
__device__ float g_Q[(size_t)M_ * D_];                 // 32 MB
__device__ float g_K[(size_t)M_ * D_];                 // 32 MB
__device__ float g_V[(size_t)M_ * D_];                 // 32 MB
__device__ float g_Tp[(size_t)B_ * H_ * 8 * DK_ * DK_]; // split-K partials of K^T V
__device__ float g_T [(size_t)B_ * H_ * DK_ * DK_];     // K^T V per (b,h)

// ---------------------------------------------------------------------------
// Kernel 1: fused QKV projection.  C[m,n] = sum_k X[m,k] * W[n,k]
// Classic 128x128x8 SIMT fp32 GEMM, 8x8 microtile, 256 threads.
// blockIdx.z selects which weight/output (0=Q, 1=K, 2=V).
// ---------------------------------------------------------------------------
__global__ __launch_bounds__(256) void qkv_gemm(
    const float* __restrict__ X,
    const float* __restrict__ Wq,
    const float* __restrict__ Wk,
    const float* __restrict__ Wv)
{
    const float* W = (blockIdx.z == 0) ? Wq : (blockIdx.z == 1) ? Wk : Wv;
    float*       C = (blockIdx.z == 0) ? g_Q : (blockIdx.z == 1) ? g_K : g_V;

    const int BM = 128, BN = 128, BK = 8;
    __shared__ float As[BK][BM];
    __shared__ float Bs[BK][BN];

    int tid     = threadIdx.x;
    int loadRow = tid >> 1;          // 0..127
    int loadK   = (tid & 1) * 4;     // 0 or 4

    const float* Xg = X + ((size_t)(blockIdx.y * BM + loadRow)) * D_ + loadK;
    const float* Wg = W + ((size_t)(blockIdx.x * BN + loadRow)) * D_ + loadK;

    int tr = tid >> 4;   // 0..15
    int tc = tid & 15;   // 0..15

    float acc[8][8];
#pragma unroll
    for (int i = 0; i < 8; i++)
#pragma unroll
        for (int j = 0; j < 8; j++) acc[i][j] = 0.f;

    for (int k0 = 0; k0 < D_; k0 += BK) {
        float4 xa = *(const float4*)(Xg + k0);
        float4 wa = *(const float4*)(Wg + k0);
        As[loadK + 0][loadRow] = xa.x;
        As[loadK + 1][loadRow] = xa.y;
        As[loadK + 2][loadRow] = xa.z;
        As[loadK + 3][loadRow] = xa.w;
        Bs[loadK + 0][loadRow] = wa.x;
        Bs[loadK + 1][loadRow] = wa.y;
        Bs[loadK + 2][loadRow] = wa.z;
        Bs[loadK + 3][loadRow] = wa.w;
        __syncthreads();

#pragma unroll
        for (int kk = 0; kk < BK; kk++) {
            float rm[8], rn[8];
#pragma unroll
            for (int i = 0; i < 8; i++) rm[i] = As[kk][tr * 8 + i];
#pragma unroll
            for (int j = 0; j < 8; j++) rn[j] = Bs[kk][tc * 8 + j];
#pragma unroll
            for (int i = 0; i < 8; i++)
#pragma unroll
                for (int j = 0; j < 8; j++)
                    acc[i][j] = fmaf(rm[i], rn[j], acc[i][j]);
        }
        __syncthreads();
    }

    size_t crow = (size_t)(blockIdx.y * BM + tr * 8);
    int    ccol = blockIdx.x * BN + tc * 8;
#pragma unroll
    for (int i = 0; i < 8; i++) {
        *(float4*)(C + (crow + i) * D_ + ccol)     =
            make_float4(acc[i][0], acc[i][1], acc[i][2], acc[i][3]);
        *(float4*)(C + (crow + i) * D_ + ccol + 4) =
            make_float4(acc[i][4], acc[i][5], acc[i][6], acc[i][7]);
    }
}

// ---------------------------------------------------------------------------
// Kernel 2: split-K partials of T_bh = K_bh^T @ V_bh  (64x64 per (b,h))
// grid = (64 bh, 8 splits), 256 threads, each thread owns a 4x4 tile.
// ---------------------------------------------------------------------------
__global__ __launch_bounds__(256) void kt_partial()
{
    int bh = blockIdx.x;
    int b  = bh >> 4;
    int h  = bh & 15;
    int sp = blockIdx.y;

    __shared__ float Ks[64][68];
    __shared__ float Vs[64][68];

    int tid = threadIdx.x;
    int ti  = tid >> 4;     // 0..15
    int tj  = tid & 15;     // 0..15

    float acc[4][4];
#pragma unroll
    for (int i = 0; i < 4; i++)
#pragma unroll
        for (int j = 0; j < 4; j++) acc[i][j] = 0.f;

    size_t base = ((size_t)b * S_) * D_ + h * DK_;
    int lr = tid >> 4;          // 0..15
    int lc = (tid & 15) * 4;    // 0..60 step 4

    for (int s0 = sp * 256; s0 < sp * 256 + 256; s0 += 64) {
#pragma unroll
        for (int r = lr; r < 64; r += 16) {
            float4 kv = *(const float4*)(g_K + base + (size_t)(s0 + r) * D_ + lc);
            float4 vv = *(const float4*)(g_V + base + (size_t)(s0 + r) * D_ + lc);
            Ks[r][lc] = kv.x; Ks[r][lc+1] = kv.y; Ks[r][lc+2] = kv.z; Ks[r][lc+3] = kv.w;
            Vs[r][lc] = vv.x; Vs[r][lc+1] = vv.y; Vs[r][lc+2] = vv.z; Vs[r][lc+3] = vv.w;
        }
        __syncthreads();

#pragma unroll 8
        for (int s = 0; s < 64; s++) {
            float kr[4], vr[4];
#pragma unroll
            for (int i = 0; i < 4; i++) kr[i] = Ks[s][ti * 4 + i];
#pragma unroll
            for (int j = 0; j < 4; j++) vr[j] = Vs[s][tj * 4 + j];
#pragma unroll
            for (int i = 0; i < 4; i++)
#pragma unroll
                for (int j = 0; j < 4; j++)
                    acc[i][j] = fmaf(kr[i], vr[j], acc[i][j]);
        }
        __syncthreads();
    }

    float* Tp = g_Tp + ((size_t)bh * 8 + sp) * (DK_ * DK_);
#pragma unroll
    for (int i = 0; i < 4; i++)
#pragma unroll
        for (int j = 0; j < 4; j++)
            Tp[(ti * 4 + i) * DK_ + tj * 4 + j] = acc[i][j];
}

// ---------------------------------------------------------------------------
// Kernel 3: reduce the 8 split-K partials into g_T
// ---------------------------------------------------------------------------
__global__ __launch_bounds__(256) void kt_reduce()
{
    int bh = blockIdx.x;
    for (int e = threadIdx.x; e < DK_ * DK_; e += 256) {
        float s = 0.f;
#pragma unroll
        for (int p = 0; p < 8; p++)
            s += g_Tp[((size_t)bh * 8 + p) * (DK_ * DK_) + e];
        g_T[(size_t)bh * (DK_ * DK_) + e] = s;
    }
}

// ---------------------------------------------------------------------------
// Kernel 4: out[b,s,h*64+d] = (1/8) * sum_j Q[b,s,h*64+j] * T_bh[j,d]
// grid = B*H*(S/64) = 2048 blocks, 256 threads.
// ---------------------------------------------------------------------------
__global__ __launch_bounds__(256) void attn_out(float* __restrict__ out)
{
    int bid = blockIdx.x;
    int b   = bid >> 9;         // 512 blocks per batch (16 heads * 32 s-tiles)
    int h   = (bid >> 5) & 15;
    int st  = bid & 31;

    __shared__ float Ts[64][68];
    __shared__ float Qs[64][68];

    int tid = threadIdx.x;

    // Load T_bh (4096 floats)
    {
        const float* T = g_T + (size_t)(b * H_ + h) * (DK_ * DK_);
        for (int e = tid; e < DK_ * DK_; e += 256)
            Ts[e >> 6][e & 63] = T[e];
    }
    // Load Q tile: rows st*64 .. +63, cols h*64 .. +63
    {
        size_t qbase = ((size_t)b * S_ + st * 64) * D_ + h * DK_;
        int lr = tid >> 4;
        int lc = (tid & 15) * 4;
#pragma unroll
        for (int r = lr; r < 64; r += 16) {
            float4 qv = *(const float4*)(g_Q + qbase + (size_t)r * D_ + lc);
            Qs[r][lc] = qv.x; Qs[r][lc+1] = qv.y; Qs[r][lc+2] = qv.z; Qs[r][lc+3] = qv.w;
        }
    }
    __syncthreads();

    int sl = tid >> 2;            // 0..63 : local s row
    int dg = (tid & 3) * 16;      // 0,16,32,48 : d group

    float acc[16];
#pragma unroll
    for (int d = 0; d < 16; d++) acc[d] = 0.f;

#pragma unroll 16
    for (int j = 0; j < 64; j++) {
        float qv = Qs[sl][j];
#pragma unroll
        for (int d = 0; d < 16; d++)
            acc[d] = fmaf(qv, Ts[j][dg + d], acc[d]);
    }

    float* op = out + ((size_t)b * S_ + st * 64 + sl) * D_ + h * DK_ + dg;
#pragma unroll
    for (int d4 = 0; d4 < 16; d4 += 4)
        *(float4*)(op + d4) = make_float4(acc[d4] * 0.125f, acc[d4+1] * 0.125f,
                                          acc[d4+2] * 0.125f, acc[d4+3] * 0.125f);
}

// ---------------------------------------------------------------------------
// Kernel 5: mask correction.
// The associative form assumed every score is unmasked. For any (b,q,k) with
// mask==0 the true contribution is (-1e9)*v_k instead of score*v_k, so add
// (-1e9 - score_qk) * v_k. Fast path: scan the mask row; if no zeros, return.
// (For this dataset the mask is all ones, so only the 64 MB scan executes.)
// ---------------------------------------------------------------------------
__global__ __launch_bounds__(256) void mask_fix(const int* __restrict__ mask,
                                                float* __restrict__ out)
{
    int bq = blockIdx.x;              // 0 .. B*S-1
    int b  = bq >> 11;
    const int* mrow = mask + (size_t)bq * S_;

    bool z = false;
    for (int k = threadIdx.x; k < S_; k += 256)
        z |= (mrow[k] == 0);
    if (!__syncthreads_or(z)) return;   // fast path: row fully unmasked

    // ---- slow path (generic correctness; not exercised by this dataset) ----
    __shared__ float sc[H_];
    size_t qoff = (size_t)bq * D_;
    int wid  = threadIdx.x >> 5;
    int lane = threadIdx.x & 31;

    for (int k = 0; k < S_; k++) {
        if (mrow[k] != 0) continue;
        size_t koff = ((size_t)b * S_ + k) * D_;
        if (wid < 8) {
#pragma unroll
            for (int hh = 0; hh < 2; hh++) {
                int h = wid * 2 + hh;
                float p = g_Q[qoff + h * DK_ + lane]      * g_K[koff + h * DK_ + lane]
                        + g_Q[qoff + h * DK_ + 32 + lane] * g_K[koff + h * DK_ + 32 + lane];
#pragma unroll
                for (int o = 16; o > 0; o >>= 1)
                    p += __shfl_down_sync(0xffffffffu, p, o);
                if (lane == 0) sc[h] = p * 0.125f;
            }
        }
        __syncthreads();
        for (int idx = threadIdx.x; idx < D_; idx += 256) {
            int h = idx >> 6;
            out[qoff + idx] += (-1e9f - sc[h]) * g_V[koff + idx];
        }
        __syncthreads();
    }
}

// ---------------------------------------------------------------------------
// Entry point
// Inputs (metadata order): x [B,S,D] f32, mask [B,S,S] i32,
//                          wq [D,D] f32, wk [D,D] f32, wv [D,D] f32
// Output: [B,S,D] f32
// ---------------------------------------------------------------------------
extern "C" void kernel_launch(void* const* d_in, const int* in_sizes, int n_in,
                              void* d_out, int out_size)
{
    const float* x    = (const float*)d_in[0];
    const int*   mask = (const int*)  d_in[1];
    const float* wq   = (const float*)d_in[2];
    const float* wk   = (const float*)d_in[3];
    const float* wv   = (const float*)d_in[4];
    float*       out  = (float*)d_out;

    // 1) Q,K,V projections (fused grid, z selects weight)
    qkv_gemm<<<dim3(D_ / 128, M_ / 128, 3), 256>>>(x, wq, wk, wv);
    // 2) T_bh = K_bh^T V_bh, split-K over S then reduce
    kt_partial<<<dim3(B_ * H_, 8), 256>>>();
    kt_reduce<<<B_ * H_, 256>>>();
    // 3) out = Q @ T / 8
    attn_out<<<B_ * H_ * (S_ / 64), 256>>>(out);
    // 4) generic mask handling (fast scan when mask has no zeros)
    mask_fix<<<B_ * S_, 256>>>(mask, out);
}

// round 3
// speedup vs baseline: 2.2693x; 2.2693x over previous
#include <cuda_runtime.h>
#include <cuda_bf16.h>
#include <cstdint>

// Problem constants (fixed by dataset: B=4, S=2048, D=1024, H=16)
#define B_  4
#define S_  2048
#define D_  1024
#define H_  16
#define DK_ 64
#define M_  (B_ * S_)   // 8192

// ---------------------------------------------------------------------------
// Device-global scratch (no allocations allowed anywhere)
// ---------------------------------------------------------------------------
__device__ float g_Q[(size_t)M_ * D_];
__device__ float g_K[(size_t)M_ * D_];
__device__ float g_V[(size_t)M_ * D_];
__device__ float g_Tp[(size_t)B_ * H_ * 8 * DK_ * DK_];
__device__ float g_T [(size_t)B_ * H_ * DK_ * DK_];
__device__ __nv_bfloat16 g_Xhi[(size_t)M_ * D_];
__device__ __nv_bfloat16 g_Xlo[(size_t)M_ * D_];
__device__ __nv_bfloat16 g_Whi[3 * (size_t)D_ * D_];
__device__ __nv_bfloat16 g_Wlo[3 * (size_t)D_ * D_];

// ---------------------------------------------------------------------------
// Helpers
// ---------------------------------------------------------------------------
__device__ __forceinline__ uint32_t smem_u32(const void* p) {
    uint32_t a;
    asm("{ .reg .u64 t; cvta.to.shared.u64 t, %1; cvt.u32.u64 %0, t; }"
        : "=r"(a) : "l"(p));
    return a;
}
__device__ __forceinline__ void cp16(uint32_t saddr, const void* gptr) {
    asm volatile("cp.async.ca.shared.global [%0], [%1], 16;"
                 :: "r"(saddr), "l"(gptr) : "memory");
}
__device__ __forceinline__ void cp_commit() {
    asm volatile("cp.async.commit_group;" ::: "memory");
}
template <int N>
__device__ __forceinline__ void cp_wait() {
    asm volatile("cp.async.wait_group %0;" :: "n"(N) : "memory");
}
__device__ __forceinline__ void ldsm4(uint32_t* r, uint32_t addr) {
    asm volatile("ldmatrix.sync.aligned.m8n8.x4.shared.b16 {%0,%1,%2,%3}, [%4];"
                 : "=r"(r[0]), "=r"(r[1]), "=r"(r[2]), "=r"(r[3]) : "r"(addr));
}
__device__ __forceinline__ void mma16816(float* d, const uint32_t* a,
                                         uint32_t b0, uint32_t b1) {
    asm volatile(
        "mma.sync.aligned.m16n8k16.row.col.f32.bf16.bf16.f32 "
        "{%0,%1,%2,%3}, {%4,%5,%6,%7}, {%8,%9}, {%0,%1,%2,%3};"
        : "+f"(d[0]), "+f"(d[1]), "+f"(d[2]), "+f"(d[3])
        : "r"(a[0]), "r"(a[1]), "r"(a[2]), "r"(a[3]), "r"(b0), "r"(b1));
}

// ---------------------------------------------------------------------------
// Kernel 0: split fp32 -> bf16 hi + bf16 lo (residual)
// ---------------------------------------------------------------------------
__global__ __launch_bounds__(256) void bf16_split(const float* __restrict__ src,
                                                  int which, int n4)
{
    int i = blockIdx.x * 256 + threadIdx.x;
    if (i >= n4) return;
    __nv_bfloat16* hi = (which == 0) ? g_Xhi : g_Whi + (size_t)(which - 1) * D_ * D_;
    __nv_bfloat16* lo = (which == 0) ? g_Xlo : g_Wlo + (size_t)(which - 1) * D_ * D_;
    float4 v = ((const float4*)src)[i];
    __nv_bfloat16 h0 = __float2bfloat16_rn(v.x);
    __nv_bfloat16 h1 = __float2bfloat16_rn(v.y);
    __nv_bfloat16 h2 = __float2bfloat16_rn(v.z);
    __nv_bfloat16 h3 = __float2bfloat16_rn(v.w);
    __nv_bfloat16 l0 = __float2bfloat16_rn(v.x - __bfloat162float(h0));
    __nv_bfloat16 l1 = __float2bfloat16_rn(v.y - __bfloat162float(h1));
    __nv_bfloat16 l2 = __float2bfloat16_rn(v.z - __bfloat162float(h2));
    __nv_bfloat16 l3 = __float2bfloat16_rn(v.w - __bfloat162float(h3));
    __nv_bfloat162* hp = (__nv_bfloat162*)hi + (size_t)i * 2;
    __nv_bfloat162* lp = (__nv_bfloat162*)lo + (size_t)i * 2;
    hp[0] = __halves2bfloat162(h0, h1);
    hp[1] = __halves2bfloat162(h2, h3);
    lp[0] = __halves2bfloat162(l0, l1);
    lp[1] = __halves2bfloat162(l2, l3);
}

// ---------------------------------------------------------------------------
// Kernel 1: bf16x3 projection GEMM on mma.sync (HMMA).
// C[m,n] = sum_k X[m,k] W[n,k]  as  Xh@Wh^T + Xh@Wl^T + Xl@Wh^T
// BM=128 BN=128 BK=32, 256 thr (warps 4m x 2n), cp.async double buffer.
// grid = (N/128, M/128, 3)
// ---------------------------------------------------------------------------
#define PAD_ROW   80                      // bytes per 32-bf16 row (64B data + 16B pad)
#define MAT_BYTES (128 * PAD_ROW)         // 10240
#define STAGE_B   (4 * MAT_BYTES)         // Ah|Al|Bh|Bl = 40960
#define GEMM_SMEM (2 * STAGE_B)           // 81920
#define NC_       32                      // 1024 / 32 k-chunks

__global__ __launch_bounds__(256, 1) void qkv_mma(void)
{
    extern __shared__ char dsm[];
    const uint32_t sbase = smem_u32(dsm);

    const int tid  = threadIdx.x;
    const int lane = tid & 31;
    const int wid  = tid >> 5;
    const int wm   = wid & 3;          // 0..3 -> 32 rows each
    const int wn   = wid >> 2;         // 0..1 -> 64 cols each
    const int z    = blockIdx.z;
    const int m0   = blockIdx.y * 128;
    const int n0   = blockIdx.x * 128;

    const __nv_bfloat16* __restrict__ Ah = g_Xhi + (size_t)m0 * D_;
    const __nv_bfloat16* __restrict__ Al = g_Xlo + (size_t)m0 * D_;
    const __nv_bfloat16* __restrict__ Bh = g_Whi + (size_t)z * D_ * D_ + (size_t)n0 * D_;
    const __nv_bfloat16* __restrict__ Bl = g_Wlo + (size_t)z * D_ * D_ + (size_t)n0 * D_;
    float* __restrict__ C = (z == 0) ? g_Q : (z == 1) ? g_K : g_V;

    // load indices: 512 16B segments per matrix per chunk; 2 per thread
    const int r0 = (tid + 0)   >> 2, s0 = (tid + 0)   & 3;
    const int r1 = (tid + 256) >> 2, s1 = (tid + 256) & 3;

    auto load_chunk = [&](int buf, int k0) {
        uint32_t st = sbase + buf * STAGE_B;
        // Ah, Al
        cp16(st + r0 * PAD_ROW + s0 * 16,                 Ah + (size_t)r0 * D_ + k0 + s0 * 8);
        cp16(st + r1 * PAD_ROW + s1 * 16,                 Ah + (size_t)r1 * D_ + k0 + s1 * 8);
        cp16(st + MAT_BYTES + r0 * PAD_ROW + s0 * 16,     Al + (size_t)r0 * D_ + k0 + s0 * 8);
        cp16(st + MAT_BYTES + r1 * PAD_ROW + s1 * 16,     Al + (size_t)r1 * D_ + k0 + s1 * 8);
        // Bh, Bl
        cp16(st + 2 * MAT_BYTES + r0 * PAD_ROW + s0 * 16, Bh + (size_t)r0 * D_ + k0 + s0 * 8);
        cp16(st + 2 * MAT_BYTES + r1 * PAD_ROW + s1 * 16, Bh + (size_t)r1 * D_ + k0 + s1 * 8);
        cp16(st + 3 * MAT_BYTES + r0 * PAD_ROW + s0 * 16, Bl + (size_t)r0 * D_ + k0 + s0 * 8);
        cp16(st + 3 * MAT_BYTES + r1 * PAD_ROW + s1 * 16, Bl + (size_t)r1 * D_ + k0 + s1 * 8);
        cp_commit();
    };

    float acc[2][8][4];
#pragma unroll
    for (int mt = 0; mt < 2; mt++)
#pragma unroll
        for (int nt = 0; nt < 8; nt++)
#pragma unroll
            for (int e = 0; e < 4; e++) acc[mt][nt][e] = 0.f;

    load_chunk(0, 0);

    const int arow  = lane & 15;
    const int aksel = lane >> 4;                       // 0/1 -> +8 cols
    const int brow  = (lane & 7) + 8 * ((lane >> 3) & 1);
    const int bksel = lane >> 4;

    for (int c = 0; c < NC_; c++) {
        const int buf = c & 1;
        if (c + 1 < NC_) {
            load_chunk(buf ^ 1, (c + 1) * 32);
            cp_wait<1>();
        } else {
            cp_wait<0>();
        }
        __syncthreads();

        const uint32_t st = sbase + buf * STAGE_B;
#pragma unroll
        for (int ks = 0; ks < 2; ks++) {
            const int k0 = ks * 16;
            uint32_t ah[2][4], al[2][4], bh[4][4], bl[4][4];
#pragma unroll
            for (int mt = 0; mt < 2; mt++) {
                uint32_t ad = st + (wm * 32 + mt * 16 + arow) * PAD_ROW
                            + (k0 + aksel * 8) * 2;
                ldsm4(ah[mt], ad);
                ldsm4(al[mt], ad + MAT_BYTES);
            }
#pragma unroll
            for (int ng = 0; ng < 4; ng++) {
                uint32_t bd = st + 2 * MAT_BYTES
                            + (wn * 64 + ng * 16 + brow) * PAD_ROW
                            + (k0 + bksel * 8) * 2;
                ldsm4(bh[ng], bd);
                ldsm4(bl[ng], bd + MAT_BYTES);
            }
#pragma unroll
            for (int mt = 0; mt < 2; mt++)
#pragma unroll
                for (int nt = 0; nt < 8; nt++) {
                    const int ng = nt >> 1, w = nt & 1;
                    mma16816(acc[mt][nt], ah[mt], bh[ng][w], bh[ng][w + 2]); // hi*hi
                    mma16816(acc[mt][nt], ah[mt], bl[ng][w], bl[ng][w + 2]); // hi*lo
                    mma16816(acc[mt][nt], al[mt], bh[ng][w], bh[ng][w + 2]); // lo*hi
                }
        }
        __syncthreads();
    }

    // Epilogue: fragment layout of m16n8 -> rows lane>>2 / +8, cols (lane&3)*2
#pragma unroll
    for (int mt = 0; mt < 2; mt++) {
        const int rbase = m0 + wm * 32 + mt * 16 + (lane >> 2);
#pragma unroll
        for (int nt = 0; nt < 8; nt++) {
            const int col = n0 + wn * 64 + nt * 8 + (lane & 3) * 2;
            *(float2*)(C + (size_t)rbase * D_ + col) =
                make_float2(acc[mt][nt][0], acc[mt][nt][1]);
            *(float2*)(C + (size_t)(rbase + 8) * D_ + col) =
                make_float2(acc[mt][nt][2], acc[mt][nt][3]);
        }
    }
}

// ---------------------------------------------------------------------------
// Kernel 2: split-K partials of T_bh = K_bh^T @ V_bh
// ---------------------------------------------------------------------------
__global__ __launch_bounds__(256) void kt_partial()
{
    int bh = blockIdx.x;
    int b  = bh >> 4;
    int h  = bh & 15;
    int sp = blockIdx.y;

    __shared__ float Ks[64][68];
    __shared__ float Vs[64][68];

    int tid = threadIdx.x;
    int ti  = tid >> 4;
    int tj  = tid & 15;

    float acc[4][4];
#pragma unroll
    for (int i = 0; i < 4; i++)
#pragma unroll
        for (int j = 0; j < 4; j++) acc[i][j] = 0.f;

    size_t base = ((size_t)b * S_) * D_ + h * DK_;
    int lr = tid >> 4;
    int lc = (tid & 15) * 4;

    for (int s0 = sp * 256; s0 < sp * 256 + 256; s0 += 64) {
#pragma unroll
        for (int r = lr; r < 64; r += 16) {
            float4 kv = *(const float4*)(g_K + base + (size_t)(s0 + r) * D_ + lc);
            float4 vv = *(const float4*)(g_V + base + (size_t)(s0 + r) * D_ + lc);
            Ks[r][lc] = kv.x; Ks[r][lc+1] = kv.y; Ks[r][lc+2] = kv.z; Ks[r][lc+3] = kv.w;
            Vs[r][lc] = vv.x; Vs[r][lc+1] = vv.y; Vs[r][lc+2] = vv.z; Vs[r][lc+3] = vv.w;
        }
        __syncthreads();
#pragma unroll 8
        for (int s = 0; s < 64; s++) {
            float kr[4], vr[4];
#pragma unroll
            for (int i = 0; i < 4; i++) kr[i] = Ks[s][ti * 4 + i];
#pragma unroll
            for (int j = 0; j < 4; j++) vr[j] = Vs[s][tj * 4 + j];
#pragma unroll
            for (int i = 0; i < 4; i++)
#pragma unroll
                for (int j = 0; j < 4; j++)
                    acc[i][j] = fmaf(kr[i], vr[j], acc[i][j]);
        }
        __syncthreads();
    }

    float* Tp = g_Tp + ((size_t)bh * 8 + sp) * (DK_ * DK_);
#pragma unroll
    for (int i = 0; i < 4; i++)
#pragma unroll
        for (int j = 0; j < 4; j++)
            Tp[(ti * 4 + i) * DK_ + tj * 4 + j] = acc[i][j];
}

__global__ __launch_bounds__(256) void kt_reduce()
{
    int bh = blockIdx.x;
    for (int e = threadIdx.x; e < DK_ * DK_; e += 256) {
        float s = 0.f;
#pragma unroll
        for (int p = 0; p < 8; p++)
            s += g_Tp[((size_t)bh * 8 + p) * (DK_ * DK_) + e];
        g_T[(size_t)bh * (DK_ * DK_) + e] = s;
    }
}

// ---------------------------------------------------------------------------
// Kernel 3: out = (Q @ T_bh) / 8. 256x64 tile per block, 8x8 microtile.
// ---------------------------------------------------------------------------
#define ATTN_SMEM ((64 * 64 + 64 * 260) * 4)
__global__ __launch_bounds__(256) void attn_out2(float* __restrict__ out)
{
    extern __shared__ float sm2[];
    float* Ts = sm2;             // [64][64]
    float* Qt = sm2 + 64 * 64;   // [64][260]  Q^T

    int bid = blockIdx.x;
    int b  = bid >> 7;
    int h  = (bid >> 3) & 15;
    int st = bid & 7;
    int tid = threadIdx.x;

    const float* T = g_T + (size_t)(b * H_ + h) * (DK_ * DK_);
    for (int e = tid; e < 4096; e += 256) Ts[e] = T[e];

    size_t qbase = ((size_t)b * S_ + st * 256) * D_ + h * 64;
    for (int i = tid; i < 4096; i += 256) {
        int r = i >> 4, jj = (i & 15) << 2;
        float4 q = *(const float4*)(g_Q + qbase + (size_t)r * D_ + jj);
        Qt[(jj + 0) * 260 + r] = q.x;
        Qt[(jj + 1) * 260 + r] = q.y;
        Qt[(jj + 2) * 260 + r] = q.z;
        Qt[(jj + 3) * 260 + r] = q.w;
    }
    __syncthreads();

    int tr = tid >> 3;
    int tc = tid & 7;
    float acc[8][8] = {};

#pragma unroll 4
    for (int j = 0; j < 64; j++) {
        float4 a0 = *(const float4*)(Qt + j * 260 + tr * 8);
        float4 a1 = *(const float4*)(Qt + j * 260 + tr * 8 + 4);
        float4 b0 = *(const float4*)(Ts + j * 64 + tc * 8);
        float4 b1 = *(const float4*)(Ts + j * 64 + tc * 8 + 4);
        float rm[8] = {a0.x, a0.y, a0.z, a0.w, a1.x, a1.y, a1.z, a1.w};
        float rn[8] = {b0.x, b0.y, b0.z, b0.w, b1.x, b1.y, b1.z, b1.w};
#pragma unroll
        for (int i = 0; i < 8; i++)
#pragma unroll
            for (int n = 0; n < 8; n++)
                acc[i][n] = fmaf(rm[i], rn[n], acc[i][n]);
    }

#pragma unroll
    for (int i = 0; i < 8; i++) {
        size_t row = (size_t)b * S_ + st * 256 + tr * 8 + i;
        float* op = out + row * D_ + h * 64 + tc * 8;
        *(float4*)op       = make_float4(acc[i][0] * .125f, acc[i][1] * .125f,
                                         acc[i][2] * .125f, acc[i][3] * .125f);
        *(float4*)(op + 4) = make_float4(acc[i][4] * .125f, acc[i][5] * .125f,
                                         acc[i][6] * .125f, acc[i][7] * .125f);
    }
}

// ---------------------------------------------------------------------------
// Kernel 4: mask correction (fast scan when mask has no zeros)
// ---------------------------------------------------------------------------
__global__ __launch_bounds__(256) void mask_fix(const int* __restrict__ mask,
                                                float* __restrict__ out)
{
    int bq = blockIdx.x;
    int b  = bq >> 11;
    const int* mrow = mask + (size_t)bq * S_;

    bool zf = false;
    for (int k = threadIdx.x; k < S_; k += 256)
        zf |= (mrow[k] == 0);
    if (!__syncthreads_or(zf)) return;

    __shared__ float sc[H_];
    size_t qoff = (size_t)bq * D_;
    int wid  = threadIdx.x >> 5;
    int lane = threadIdx.x & 31;

    for (int k = 0; k < S_; k++) {
        if (mrow[k] != 0) continue;
        size_t koff = ((size_t)b * S_ + k) * D_;
        if (wid < 8) {
#pragma unroll
            for (int hh = 0; hh < 2; hh++) {
                int h = wid * 2 + hh;
                float p = g_Q[qoff + h * DK_ + lane]      * g_K[koff + h * DK_ + lane]
                        + g_Q[qoff + h * DK_ + 32 + lane] * g_K[koff + h * DK_ + 32 + lane];
#pragma unroll
                for (int o = 16; o > 0; o >>= 1)
                    p += __shfl_down_sync(0xffffffffu, p, o);
                if (lane == 0) sc[h] = p * 0.125f;
            }
        }
        __syncthreads();
        for (int idx = threadIdx.x; idx < D_; idx += 256) {
            int h = idx >> 6;
            out[qoff + idx] += (-1e9f - sc[h]) * g_V[koff + idx];
        }
        __syncthreads();
    }
}

// ---------------------------------------------------------------------------
// Entry point
// ---------------------------------------------------------------------------
extern "C" void kernel_launch(void* const* d_in, const int* in_sizes, int n_in,
                              void* d_out, int out_size)
{
    const float* x    = (const float*)d_in[0];
    const int*   mask = (const int*)  d_in[1];
    const float* wq   = (const float*)d_in[2];
    const float* wk   = (const float*)d_in[3];
    const float* wv   = (const float*)d_in[4];
    float*       out  = (float*)d_out;

    cudaFuncSetAttribute(qkv_mma,   cudaFuncAttributeMaxDynamicSharedMemorySize, GEMM_SMEM);
    cudaFuncSetAttribute(attn_out2, cudaFuncAttributeMaxDynamicSharedMemorySize, ATTN_SMEM);

    // 0) split fp32 -> bf16 hi/lo
    bf16_split<<<(M_ * D_ / 4 + 255) / 256, 256>>>(x,  0, M_ * D_ / 4);
    bf16_split<<<(D_ * D_ / 4 + 255) / 256, 256>>>(wq, 1, D_ * D_ / 4);
    bf16_split<<<(D_ * D_ / 4 + 255) / 256, 256>>>(wk, 2, D_ * D_ / 4);
    bf16_split<<<(D_ * D_ / 4 + 255) / 256, 256>>>(wv, 3, D_ * D_ / 4);

    // 1) Q,K,V projections on HMMA (bf16x3)
    qkv_mma<<<dim3(D_ / 128, M_ / 128, 3), 256, GEMM_SMEM>>>();

    // 2) T_bh = K_bh^T V_bh
    kt_partial<<<dim3(B_ * H_, 8), 256>>>();
    kt_reduce<<<B_ * H_, 256>>>();

    // 3) out = Q @ T / 8
    attn_out2<<<B_ * H_ * (S_ / 256), 256, ATTN_SMEM>>>(out);

    // 4) generic mask handling
    mask_fix<<<B_ * S_, 256>>>(mask, out);
}

// round 4
// speedup vs baseline: 3.0753x; 1.3552x over previous
#include <cuda_runtime.h>
#include <cuda_fp16.h>
#include <cstdint>

// Problem constants (fixed by dataset: B=4, S=2048, D=1024, H=16)
#define B_  4
#define S_  2048
#define D_  1024
#define H_  16
#define DK_ 64
#define M_  (B_ * S_)   // 8192

// ---------------------------------------------------------------------------
// Device-global scratch
// ---------------------------------------------------------------------------
__device__ float g_Q[(size_t)M_ * D_];
__device__ float g_K[(size_t)M_ * D_];
__device__ float g_V[(size_t)M_ * D_];
__device__ float g_Tp[(size_t)B_ * H_ * 8 * DK_ * DK_];
__device__ float g_T [(size_t)B_ * H_ * DK_ * DK_];
__device__ __half g_Xh[(size_t)M_ * D_];
__device__ __half g_Wh[3 * (size_t)D_ * D_];
__device__ __half g_Wl[3 * (size_t)D_ * D_];

// ---------------------------------------------------------------------------
// Helpers
// ---------------------------------------------------------------------------
__device__ __forceinline__ uint32_t smem_u32(const void* p) {
    uint32_t a;
    asm("{ .reg .u64 t; cvta.to.shared.u64 t, %1; cvt.u32.u64 %0, t; }"
        : "=r"(a) : "l"(p));
    return a;
}
__device__ __forceinline__ void cp16(uint32_t saddr, const void* gptr) {
    asm volatile("cp.async.ca.shared.global [%0], [%1], 16;"
                 :: "r"(saddr), "l"(gptr) : "memory");
}
__device__ __forceinline__ void cp_commit() {
    asm volatile("cp.async.commit_group;" ::: "memory");
}
template <int N>
__device__ __forceinline__ void cp_wait() {
    asm volatile("cp.async.wait_group %0;" :: "n"(N) : "memory");
}
__device__ __forceinline__ void ldsm4(uint32_t* r, uint32_t addr) {
    asm volatile("ldmatrix.sync.aligned.m8n8.x4.shared.b16 {%0,%1,%2,%3}, [%4];"
                 : "=r"(r[0]), "=r"(r[1]), "=r"(r[2]), "=r"(r[3]) : "r"(addr));
}
__device__ __forceinline__ void mma16816(float* d, const uint32_t* a,
                                         uint32_t b0, uint32_t b1) {
    asm volatile(
        "mma.sync.aligned.m16n8k16.row.col.f32.f16.f16.f32 "
        "{%0,%1,%2,%3}, {%4,%5,%6,%7}, {%8,%9}, {%0,%1,%2,%3};"
        : "+f"(d[0]), "+f"(d[1]), "+f"(d[2]), "+f"(d[3])
        : "r"(a[0]), "r"(a[1]), "r"(a[2]), "r"(a[3]), "r"(b0), "r"(b1));
}

// ---------------------------------------------------------------------------
// Kernel 0a: X fp32 -> fp16 hi only
// ---------------------------------------------------------------------------
__global__ __launch_bounds__(256) void f16_split_x(const float* __restrict__ src,
                                                   int n4)
{
    int i = blockIdx.x * 256 + threadIdx.x;
    if (i >= n4) return;
    float4 v = ((const float4*)src)[i];
    __half2* hp = (__half2*)g_Xh + (size_t)i * 2;
    hp[0] = __halves2half2(__float2half_rn(v.x), __float2half_rn(v.y));
    hp[1] = __halves2half2(__float2half_rn(v.z), __float2half_rn(v.w));
}

// Kernel 0b: W fp32 -> fp16 hi + lo (residual)
__global__ __launch_bounds__(256) void f16_split_w(const float* __restrict__ src,
                                                   int slot, int n4)
{
    int i = blockIdx.x * 256 + threadIdx.x;
    if (i >= n4) return;
    __half* hi = g_Wh + (size_t)slot * D_ * D_;
    __half* lo = g_Wl + (size_t)slot * D_ * D_;
    float4 v = ((const float4*)src)[i];
    __half h0 = __float2half_rn(v.x), h1 = __float2half_rn(v.y);
    __half h2 = __float2half_rn(v.z), h3 = __float2half_rn(v.w);
    __half l0 = __float2half_rn(v.x - __half2float(h0));
    __half l1 = __float2half_rn(v.y - __half2float(h1));
    __half l2 = __float2half_rn(v.z - __half2float(h2));
    __half l3 = __float2half_rn(v.w - __half2float(h3));
    __half2* hp = (__half2*)hi + (size_t)i * 2;
    __half2* lp = (__half2*)lo + (size_t)i * 2;
    hp[0] = __halves2half2(h0, h1); hp[1] = __halves2half2(h2, h3);
    lp[0] = __halves2half2(l0, l1); lp[1] = __halves2half2(l2, l3);
}

// ---------------------------------------------------------------------------
// Kernel 1: fp16 2-term projection GEMM on mma.sync.
// C[m,n] = sum_k X[m,k] W[n,k] ≈ Xh@Wh^T + Xh@Wl^T
// BM=128 BN=128 BK=32, 3-stage cp.async, 256 thr (warps 4m x 2n), 2 CTAs/SM.
// grid = (8, 64, 3)
// ---------------------------------------------------------------------------
#define PAD_ROW   80                      // 64B data + 16B pad per 32-half row
#define MAT_BYTES (128 * PAD_ROW)         // 10240
#define STAGE_B   (3 * MAT_BYTES)         // Ah|Bh|Bl = 30720
#define N_STAGES  3
#define GEMM_SMEM (N_STAGES * STAGE_B)    // 92160
#define NC_       32                      // 1024/32 k-chunks

__global__ __launch_bounds__(256, 2) void qkv_mma(void)
{
    extern __shared__ char dsm[];
    const uint32_t sbase = smem_u32(dsm);

    const int tid  = threadIdx.x;
    const int lane = tid & 31;
    const int wid  = tid >> 5;
    const int wm   = wid & 3;          // 0..3 -> 32 rows
    const int wn   = wid >> 2;         // 0..1 -> 64 cols
    const int z    = blockIdx.z;
    const int m0   = blockIdx.y * 128;
    const int n0   = blockIdx.x * 128;

    const __half* __restrict__ Ah = g_Xh + (size_t)m0 * D_;
    const __half* __restrict__ Bh = g_Wh + (size_t)z * D_ * D_ + (size_t)n0 * D_;
    const __half* __restrict__ Bl = g_Wl + (size_t)z * D_ * D_ + (size_t)n0 * D_;
    float* __restrict__ C = (z == 0) ? g_Q : (z == 1) ? g_K : g_V;

    // 512 16B segments per matrix per chunk -> 2 per thread per matrix
    const int r0 = (tid + 0)   >> 2, s0 = (tid + 0)   & 3;
    const int r1 = (tid + 256) >> 2, s1 = (tid + 256) & 3;

    auto load_chunk = [&](int buf, int k0) {
        uint32_t st = sbase + buf * STAGE_B;
        cp16(st + r0 * PAD_ROW + s0 * 16,                 Ah + (size_t)r0 * D_ + k0 + s0 * 8);
        cp16(st + r1 * PAD_ROW + s1 * 16,                 Ah + (size_t)r1 * D_ + k0 + s1 * 8);
        cp16(st + MAT_BYTES + r0 * PAD_ROW + s0 * 16,     Bh + (size_t)r0 * D_ + k0 + s0 * 8);
        cp16(st + MAT_BYTES + r1 * PAD_ROW + s1 * 16,     Bh + (size_t)r1 * D_ + k0 + s1 * 8);
        cp16(st + 2 * MAT_BYTES + r0 * PAD_ROW + s0 * 16, Bl + (size_t)r0 * D_ + k0 + s0 * 8);
        cp16(st + 2 * MAT_BYTES + r1 * PAD_ROW + s1 * 16, Bl + (size_t)r1 * D_ + k0 + s1 * 8);
    };

    float acc[2][8][4];
#pragma unroll
    for (int mt = 0; mt < 2; mt++)
#pragma unroll
        for (int nt = 0; nt < 8; nt++)
#pragma unroll
            for (int e = 0; e < 4; e++) acc[mt][nt][e] = 0.f;

    // prologue: stages 0 and 1 in flight
    load_chunk(0, 0);   cp_commit();
    load_chunk(1, 32);  cp_commit();

    const int arow  = lane & 15;
    const int aksel = lane >> 4;
    const int brow  = (lane & 7) + 8 * ((lane >> 3) & 1);
    const int bksel = lane >> 4;

    for (int c = 0; c < NC_; c++) {
        const int buf = c % N_STAGES;
        cp_wait<1>();            // group for stage c complete
        __syncthreads();         // all warps done computing stage c-1
        if (c + 2 < NC_) load_chunk((c + 2) % N_STAGES, (c + 2) * 32);
        cp_commit();             // commit (possibly empty) group -> bookkeeping stays aligned

        const uint32_t st = sbase + buf * STAGE_B;
#pragma unroll
        for (int ks = 0; ks < 2; ks++) {
            const int k0 = ks * 16;
            uint32_t ah[2][4], bh[4][4], bl[4][4];
#pragma unroll
            for (int mt = 0; mt < 2; mt++) {
                uint32_t ad = st + (wm * 32 + mt * 16 + arow) * PAD_ROW
                            + (k0 + aksel * 8) * 2;
                ldsm4(ah[mt], ad);
            }
#pragma unroll
            for (int ng = 0; ng < 4; ng++) {
                uint32_t bd = st + MAT_BYTES
                            + (wn * 64 + ng * 16 + brow) * PAD_ROW
                            + (k0 + bksel * 8) * 2;
                ldsm4(bh[ng], bd);
                ldsm4(bl[ng], bd + MAT_BYTES);
            }
#pragma unroll
            for (int mt = 0; mt < 2; mt++)
#pragma unroll
                for (int nt = 0; nt < 8; nt++) {
                    const int ng = nt >> 1, w = nt & 1;
                    mma16816(acc[mt][nt], ah[mt], bh[ng][w], bh[ng][w + 2]); // hi*hi
                    mma16816(acc[mt][nt], ah[mt], bl[ng][w], bl[ng][w + 2]); // hi*lo
                }
        }
        __syncthreads();
    }

    // Epilogue
#pragma unroll
    for (int mt = 0; mt < 2; mt++) {
        const int rbase = m0 + wm * 32 + mt * 16 + (lane >> 2);
#pragma unroll
        for (int nt = 0; nt < 8; nt++) {
            const int col = n0 + wn * 64 + nt * 8 + (lane & 3) * 2;
            *(float2*)(C + (size_t)rbase * D_ + col) =
                make_float2(acc[mt][nt][0], acc[mt][nt][1]);
            *(float2*)(C + (size_t)(rbase + 8) * D_ + col) =
                make_float2(acc[mt][nt][2], acc[mt][nt][3]);
        }
    }
}

// ---------------------------------------------------------------------------
// Kernel 2: split-K partials of T_bh = K_bh^T @ V_bh
// ---------------------------------------------------------------------------
__global__ __launch_bounds__(256) void kt_partial()
{
    int bh = blockIdx.x;
    int b  = bh >> 4;
    int h  = bh & 15;
    int sp = blockIdx.y;

    __shared__ float Ks[64][68];
    __shared__ float Vs[64][68];

    int tid = threadIdx.x;
    int ti  = tid >> 4;
    int tj  = tid & 15;

    float acc[4][4];
#pragma unroll
    for (int i = 0; i < 4; i++)
#pragma unroll
        for (int j = 0; j < 4; j++) acc[i][j] = 0.f;

    size_t base = ((size_t)b * S_) * D_ + h * DK_;
    int lr = tid >> 4;
    int lc = (tid & 15) * 4;

    for (int s0 = sp * 256; s0 < sp * 256 + 256; s0 += 64) {
#pragma unroll
        for (int r = lr; r < 64; r += 16) {
            float4 kv = *(const float4*)(g_K + base + (size_t)(s0 + r) * D_ + lc);
            float4 vv = *(const float4*)(g_V + base + (size_t)(s0 + r) * D_ + lc);
            Ks[r][lc] = kv.x; Ks[r][lc+1] = kv.y; Ks[r][lc+2] = kv.z; Ks[r][lc+3] = kv.w;
            Vs[r][lc] = vv.x; Vs[r][lc+1] = vv.y; Vs[r][lc+2] = vv.z; Vs[r][lc+3] = vv.w;
        }
        __syncthreads();
#pragma unroll 8
        for (int s = 0; s < 64; s++) {
            float kr[4], vr[4];
#pragma unroll
            for (int i = 0; i < 4; i++) kr[i] = Ks[s][ti * 4 + i];
#pragma unroll
            for (int j = 0; j < 4; j++) vr[j] = Vs[s][tj * 4 + j];
#pragma unroll
            for (int i = 0; i < 4; i++)
#pragma unroll
                for (int j = 0; j < 4; j++)
                    acc[i][j] = fmaf(kr[i], vr[j], acc[i][j]);
        }
        __syncthreads();
    }

    float* Tp = g_Tp + ((size_t)bh * 8 + sp) * (DK_ * DK_);
#pragma unroll
    for (int i = 0; i < 4; i++)
#pragma unroll
        for (int j = 0; j < 4; j++)
            Tp[(ti * 4 + i) * DK_ + tj * 4 + j] = acc[i][j];
}

__global__ __launch_bounds__(256) void kt_reduce()
{
    int bh = blockIdx.x;
    for (int e = threadIdx.x; e < DK_ * DK_; e += 256) {
        float s = 0.f;
#pragma unroll
        for (int p = 0; p < 8; p++)
            s += g_Tp[((size_t)bh * 8 + p) * (DK_ * DK_) + e];
        g_T[(size_t)bh * (DK_ * DK_) + e] = s;
    }
}

// ---------------------------------------------------------------------------
// Kernel 3: out = (Q @ T_bh) / 8. 256x64 tile per block, 8x8 microtile.
// ---------------------------------------------------------------------------
#define ATTN_SMEM ((64 * 64 + 64 * 260) * 4)
__global__ __launch_bounds__(256) void attn_out2(float* __restrict__ out)
{
    extern __shared__ float sm2[];
    float* Ts = sm2;             // [64][64]
    float* Qt = sm2 + 64 * 64;   // [64][260]  Q^T

    int bid = blockIdx.x;
    int b  = bid >> 7;
    int h  = (bid >> 3) & 15;
    int st = bid & 7;
    int tid = threadIdx.x;

    const float* T = g_T + (size_t)(b * H_ + h) * (DK_ * DK_);
    for (int e = tid; e < 4096; e += 256) Ts[e] = T[e];

    size_t qbase = ((size_t)b * S_ + st * 256) * D_ + h * 64;
    for (int i = tid; i < 4096; i += 256) {
        int r = i >> 4, jj = (i & 15) << 2;
        float4 q = *(const float4*)(g_Q + qbase + (size_t)r * D_ + jj);
        Qt[(jj + 0) * 260 + r] = q.x;
        Qt[(jj + 1) * 260 + r] = q.y;
        Qt[(jj + 2) * 260 + r] = q.z;
        Qt[(jj + 3) * 260 + r] = q.w;
    }
    __syncthreads();

    int tr = tid >> 3;
    int tc = tid & 7;
    float acc[8][8] = {};

#pragma unroll 4
    for (int j = 0; j < 64; j++) {
        float4 a0 = *(const float4*)(Qt + j * 260 + tr * 8);
        float4 a1 = *(const float4*)(Qt + j * 260 + tr * 8 + 4);
        float4 b0 = *(const float4*)(Ts + j * 64 + tc * 8);
        float4 b1 = *(const float4*)(Ts + j * 64 + tc * 8 + 4);
        float rm[8] = {a0.x, a0.y, a0.z, a0.w, a1.x, a1.y, a1.z, a1.w};
        float rn[8] = {b0.x, b0.y, b0.z, b0.w, b1.x, b1.y, b1.z, b1.w};
#pragma unroll
        for (int i = 0; i < 8; i++)
#pragma unroll
            for (int n = 0; n < 8; n++)
                acc[i][n] = fmaf(rm[i], rn[n], acc[i][n]);
    }

#pragma unroll
    for (int i = 0; i < 8; i++) {
        size_t row = (size_t)b * S_ + st * 256 + tr * 8 + i;
        float* op = out + row * D_ + h * 64 + tc * 8;
        *(float4*)op       = make_float4(acc[i][0] * .125f, acc[i][1] * .125f,
                                         acc[i][2] * .125f, acc[i][3] * .125f);
        *(float4*)(op + 4) = make_float4(acc[i][4] * .125f, acc[i][5] * .125f,
                                         acc[i][6] * .125f, acc[i][7] * .125f);
    }
}

// ---------------------------------------------------------------------------
// Kernel 4: mask correction (fast scan when mask has no zeros)
// ---------------------------------------------------------------------------
__global__ __launch_bounds__(256) void mask_fix(const int* __restrict__ mask,
                                                float* __restrict__ out)
{
    int bq = blockIdx.x;
    int b  = bq >> 11;
    const int* mrow = mask + (size_t)bq * S_;

    bool zf = false;
    for (int k = threadIdx.x; k < S_; k += 256)
        zf |= (mrow[k] == 0);
    if (!__syncthreads_or(zf)) return;

    __shared__ float sc[H_];
    size_t qoff = (size_t)bq * D_;
    int wid  = threadIdx.x >> 5;
    int lane = threadIdx.x & 31;

    for (int k = 0; k < S_; k++) {
        if (mrow[k] != 0) continue;
        size_t koff = ((size_t)b * S_ + k) * D_;
        if (wid < 8) {
#pragma unroll
            for (int hh = 0; hh < 2; hh++) {
                int h = wid * 2 + hh;
                float p = g_Q[qoff + h * DK_ + lane]      * g_K[koff + h * DK_ + lane]
                        + g_Q[qoff + h * DK_ + 32 + lane] * g_K[koff + h * DK_ + 32 + lane];
#pragma unroll
                for (int o = 16; o > 0; o >>= 1)
                    p += __shfl_down_sync(0xffffffffu, p, o);
                if (lane == 0) sc[h] = p * 0.125f;
            }
        }
        __syncthreads();
        for (int idx = threadIdx.x; idx < D_; idx += 256) {
            int h = idx >> 6;
            out[qoff + idx] += (-1e9f - sc[h]) * g_V[koff + idx];
        }
        __syncthreads();
    }
}

// ---------------------------------------------------------------------------
// Entry point
// ---------------------------------------------------------------------------
extern "C" void kernel_launch(void* const* d_in, const int* in_sizes, int n_in,
                              void* d_out, int out_size)
{
    const float* x    = (const float*)d_in[0];
    const int*   mask = (const int*)  d_in[1];
    const float* wq   = (const float*)d_in[2];
    const float* wk   = (const float*)d_in[3];
    const float* wv   = (const float*)d_in[4];
    float*       out  = (float*)d_out;

    cudaFuncSetAttribute(qkv_mma,   cudaFuncAttributeMaxDynamicSharedMemorySize, GEMM_SMEM);
    cudaFuncSetAttribute(attn_out2, cudaFuncAttributeMaxDynamicSharedMemorySize, ATTN_SMEM);

    // 0) fp32 -> fp16 splits
    f16_split_x<<<(M_ * D_ / 4 + 255) / 256, 256>>>(x, M_ * D_ / 4);
    f16_split_w<<<(D_ * D_ / 4 + 255) / 256, 256>>>(wq, 0, D_ * D_ / 4);
    f16_split_w<<<(D_ * D_ / 4 + 255) / 256, 256>>>(wk, 1, D_ * D_ / 4);
    f16_split_w<<<(D_ * D_ / 4 + 255) / 256, 256>>>(wv, 2, D_ * D_ / 4);

    // 1) Q,K,V projections (fp16 2-term HMMA)
    qkv_mma<<<dim3(D_ / 128, M_ / 128, 3), 256, GEMM_SMEM>>>();

    // 2) T_bh = K_bh^T V_bh
    kt_partial<<<dim3(B_ * H_, 8), 256>>>();
    kt_reduce<<<B_ * H_, 256>>>();

    // 3) out = Q @ T / 8
    attn_out2<<<B_ * H_ * (S_ / 256), 256, ATTN_SMEM>>>(out);

    // 4) generic mask handling
    mask_fix<<<B_ * S_, 256>>>(mask, out);
}